// round 1
// baseline (speedup 1.0000x reference)
#include <cuda_runtime.h>
#include <math.h>

#define HALF_DIM 128
#define DIM 256

// inv_freq table, computed in double precision by a setup kernel each launch
// (deterministic, allocation-free, graph-capturable).
__device__ __align__(16) float g_inv_freq[HALF_DIM];

__global__ void init_freq_kernel() {
    int i = threadIdx.x;
    if (i < HALF_DIM) {
        // inv_freq_i = 10000^(-2i/256) = 2^(-i * log2(10000)/128)
        const double c = 13.287712379549449 / 128.0;  // log2(10000)/128
        g_inv_freq[i] = (float)exp2(-(double)i * c);
    }
}

__global__ __launch_bounds__(256, 8)
void sinusoidal_kernel(const float* __restrict__ x,
                       float* __restrict__ out,
                       int n_rows) {
    int tid = blockIdx.x * blockDim.x + threadIdx.x;
    int row = tid >> 5;        // one warp per row
    int j   = tid & 31;        // lane: pairs 4j .. 4j+3
    if (row >= n_rows) return;

    float xv = __ldg(x + row); // warp-broadcast load

    float4 f = *reinterpret_cast<const float4*>(g_inv_freq + 4 * j);
    float fr[4] = { f.x, f.y, f.z, f.w };

    // 2-term Cody-Waite reduction constants for 2*pi
    const float INV_2PI = 0.15915494309189535f;
    const float C1 = 6.2831854820251465f;      // fp32(2*pi)
    const float C2 = -1.7484555e-7f;           // 2*pi - C1

    float res[8];
#pragma unroll
    for (int t = 0; t < 4; t++) {
        float emb = xv * fr[t];
        float k = rintf(emb * INV_2PI);
        float r = fmaf(-k, C1, emb);
        r = fmaf(-k, C2, r);                   // |r| <= pi
        float s, c;
        __sincosf(r, &s, &c);                  // MUFU.SIN / MUFU.COS
        res[2 * t]     = s;
        res[2 * t + 1] = c;
    }

    float4* op = reinterpret_cast<float4*>(out + (size_t)row * DIM + j * 8);
    op[0] = make_float4(res[0], res[1], res[2], res[3]);
    op[1] = make_float4(res[4], res[5], res[6], res[7]);
}

extern "C" void kernel_launch(void* const* d_in, const int* in_sizes, int n_in,
                              void* d_out, int out_size) {
    const float* x = (const float*)d_in[0];
    float* out = (float*)d_out;
    int n_rows = in_sizes[0];          // 1048576

    init_freq_kernel<<<1, 128>>>();

    long long total_threads = (long long)n_rows * 32;
    int block = 256;
    int grid = (int)((total_threads + block - 1) / block);
    sinusoidal_kernel<<<grid, block>>>(x, out, n_rows);
}